// round 11
// baseline (speedup 1.0000x reference)
#include <cuda_runtime.h>
#include <cuda_fp16.h>
#include <cstdint>

#define NSYMS  256
#define NSTEPS 8192
#define NCH    62
#define HID    16

// ===========================================================================
// fp16 B fragments for mma.m16n8k16 (market cols only; k=62,63 zeroed):
//   g_Bfrag16[(ks*8+nt)*32 + lane] = { h01, h89 }
// g_Wst[0..63] = W_eff[o][sym], g_Wst[64..127] = W_eff[o][t]  (fp32, exact)
// ===========================================================================
__device__ uint2 g_Bfrag16[4 * 8 * 32];
__device__ float g_Wst[128];

__global__ void build_weff(const float* __restrict__ W1h, const float* __restrict__ M1h,
                           const float* __restrict__ W2h, const float* __restrict__ M2h,
                           const float* __restrict__ W3h, const float* __restrict__ M3h) {
    __shared__ float W1[HID * 64];
    __shared__ float W2[HID * HID];
    __shared__ float W3[64 * HID];
    __shared__ float T2[HID * 64];
    __shared__ float Wt[64 * 64];   // [cin][o]
    const int tid = threadIdx.x;

    for (int i = tid; i < HID * 64; i += 256)
        W1[i] = tanhf(W1h[i]) * (1.0f / (1.0f + expf(-M1h[i])));
    for (int i = tid; i < HID * HID; i += 256)
        W2[i] = tanhf(W2h[i]) * (1.0f / (1.0f + expf(-M2h[i])));
    for (int i = tid; i < 64 * HID; i += 256)
        W3[i] = tanhf(W3h[i]) * (1.0f / (1.0f + expf(-M3h[i])));
    __syncthreads();

    for (int i = tid; i < HID * 64; i += 256) {
        int h = i >> 6, c = i & 63;
        float s = 0.0f;
#pragma unroll
        for (int k = 0; k < HID; k++) s += W2[h * HID + k] * W1[k * 64 + c];
        T2[i] = s;
    }
    __syncthreads();

    for (int i = tid; i < 64 * 64; i += 256) {
        int o = i >> 6, c = i & 63;
        float s = 0.0f;
#pragma unroll
        for (int k = 0; k < HID; k++) s += W3[o * HID + k] * T2[k * 64 + c];
        Wt[c * 64 + o] = s;
    }
    __syncthreads();

    for (int i = tid; i < 1024; i += 256) {
        int lane = i & 31, nt = (i >> 5) & 7, ks = i >> 8;
        int g = lane >> 2, q = lane & 3;
        int n = nt * 8 + g;
        int k0 = ks * 16 + 2 * q;
        float w[4];
#pragma unroll
        for (int j = 0; j < 4; j++) {
            int k = k0 + (j >> 1) * 8 + (j & 1);
            w[j] = (k < 62) ? Wt[(k + 2) * 64 + n] : 0.0f;
        }
        __half2 h01 = __floats2half2_rn(w[0], w[1]);
        __half2 h89 = __floats2half2_rn(w[2], w[3]);
        uint2 u;
        u.x = *reinterpret_cast<uint32_t*>(&h01);
        u.y = *reinterpret_cast<uint32_t*>(&h89);
        g_Bfrag16[i] = u;
    }
    for (int i = tid; i < 128; i += 256)
        g_Wst[i] = Wt[i];
}

// ===========================================================================
// PTX helpers
// ===========================================================================
__device__ __forceinline__ void mma16816h(float& d0, float& d1, float& d2, float& d3,
                                          uint32_t a0, uint32_t a1, uint32_t a2, uint32_t a3,
                                          uint32_t b0, uint32_t b1) {
    asm volatile("mma.sync.aligned.m16n8k16.row.col.f32.f16.f16.f32 "
                 "{%0,%1,%2,%3}, {%4,%5,%6,%7}, {%8,%9}, {%0,%1,%2,%3};"
                 : "+f"(d0), "+f"(d1), "+f"(d2), "+f"(d3)
                 : "r"(a0), "r"(a1), "r"(a2), "r"(a3), "r"(b0), "r"(b1));
}
__device__ __forceinline__ void cvt_split_h(float x, float y, uint32_t& h, uint32_t& l) {
    __half2 h2 = __floats2half2_rn(x, y);
    float2 hf = __half22float2(h2);
    __half2 l2 = __floats2half2_rn(x - hf.x, y - hf.y);
    h = *reinterpret_cast<uint32_t*>(&h2);
    l = *reinterpret_cast<uint32_t*>(&l2);
}
__device__ __forceinline__ uint32_t smem_u32(const void* p) {
    uint32_t a;
    asm("{ .reg .u64 t; cvta.to.shared.u64 t, %1; cvt.u32.u64 %0, t; }" : "=r"(a) : "l"(p));
    return a;
}
#define LDMATRIX_X4(r0, r1, r2, r3, a) \
    asm volatile("ldmatrix.sync.aligned.m8n8.x4.shared.b16 {%0, %1, %2, %3}, [%4];" \
                 : "=r"(r0), "=r"(r1), "=r"(r2), "=r"(r3) : "r"(a))
#define STS32U(a, u) \
    asm volatile("st.shared.u32 [%0], %1;" :: "r"(a), "r"(u) : "memory")
#define STS64F(a, f0, f1) \
    asm volatile("st.shared.v2.f32 [%0], {%1, %2};" :: "r"(a), "f"(f0), "f"(f1) : "memory")
#define LDS128F(f0, f1, f2, f3, a) \
    asm volatile("ld.shared.v4.f32 {%0, %1, %2, %3}, [%4];" : "=f"(f0), "=f"(f1), "=f"(f2), "=f"(f3) : "r"(a))

// ===========================================================================
// Main kernel: coalesced produce (LDG.64 -> fp16 split -> swizzled smem tiles)
// + ldmatrix-fed fp16 MMA + exact fp32 affine (sym, t).
//   CTA: 256 thr = 8 warps; warp = 16 rows x 64 outs; slab = 128 rows;
//   ITERS=8 -> 1024 rows/CTA; grid 2048; 2 CTAs/SM -> 16 warps.
// smem: [0,65536) fp16 tiles (2 bufs x {Ah 16KB, Al 16KB}),
//       [65536,98304) epilogue warp tiles, [98304,98816) scorr.
// ===========================================================================
#define ITERS     8
#define SLAB_ROWS 128
#define SLAB_F2   (SLAB_ROWS * 31)   // 3968 float2 per slab
#define SM_EPI    65536
#define SM_SCORR  (SM_EPI + 32768)
#define SM_TOTAL  (SM_SCORR + 512)

__global__ void __launch_bounds__(256, 2)
encode_kernel(const float* __restrict__ market, float* __restrict__ out) {
    extern __shared__ char smem[];
    const uint32_t sb = smem_u32(smem);
    const int tid  = threadIdx.x;
    const int warp = tid >> 5;     // = row group (16 rows)
    const int lane = tid & 31;
    const int g = lane >> 2;       // 0..7
    const int q = lane & 3;        // 0..3

    // ---- B fragments: 64 regs
    uint32_t BH0[32], BH1[32];
#pragma unroll
    for (int i = 0; i < 32; i++) {
        uint2 u = g_Bfrag16[i * 32 + lane];
        BH0[i] = u.x; BH1[i] = u.y;
    }

    const long long cta_row0 = (long long)blockIdx.x * (ITERS * SLAB_ROWS);  // 1024-aligned
    const float sval = (float)(cta_row0 >> 13);
    const int   tcta = (int)(cta_row0 & (NSTEPS - 1));
    const float2* srcbase = (const float2*)((const char*)market + cta_row0 * 248);

    if (tid < 64) {
        ((float*)(smem + SM_SCORR))[tid]      = sval * g_Wst[tid];
        ((float*)(smem + SM_SCORR))[64 + tid] = g_Wst[64 + tid];
    }
    // zero the (col 62,63) pad slot in all 4 tiles (never written by produce)
    if (tid < SLAB_ROWS) {
        uint32_t off = (uint32_t)tid * 128 + (124u ^ (((uint32_t)tid & 7) << 4));
#pragma unroll
        for (int b = 0; b < 2; b++) {
            STS32U(sb + b * 32768 + off, 0u);
            STS32U(sb + b * 32768 + 16384 + off, 0u);
        }
    }

    // ---- produce slab 0 into buffer 0
    {
        const float2* src = srcbase;
        const uint32_t th = sb, tl = sb + 16384;
        for (int e = tid; e < SLAB_F2; e += 256) {
            float2 v = src[e];
            int row = e / 31;
            int cp = e - row * 31;
            uint32_t h, l;
            cvt_split_h(v.x, v.y, h, l);
            uint32_t off = (uint32_t)row * 128 +
                           (((uint32_t)cp * 4) ^ (((uint32_t)row & 7) << 4));
            STS32U(th + off, h);
            STS32U(tl + off, l);
        }
    }
    __syncthreads();

    // ldmatrix lane addressing (constant per thread):
    //   m = lane>>3 (matrix id), r8 = lane&7
    //   row = warp*16 + ((m&1)<<3) + r8 ; col byte = ks*32 + ((m>>1)<<4)
    const int m = lane >> 3, r8 = lane & 7;
    const uint32_t lrowoff = (uint32_t)(warp * 16 + ((m & 1) << 3) + r8) * 128;
    const uint32_t lswz = (uint32_t)r8 << 4;
    const uint32_t cbase = (uint32_t)((m >> 1) << 4);

    const uint32_t wb = sb + SM_EPI + warp * 4096;   // 16x64 fp32 epi tile
    const float* scorr = (const float*)(smem + SM_SCORR);

#pragma unroll 1
    for (int it = 0; it < ITERS; it++) {
        // ---- produce slab it+1 into the other buffer (overlaps MMA below)
        if (it + 1 < ITERS) {
            const float2* src = srcbase + (it + 1) * SLAB_F2;
            const uint32_t th = sb + ((it + 1) & 1) * 32768, tl = th + 16384;
            for (int e = tid; e < SLAB_F2; e += 256) {
                float2 v = src[e];
                int row = e / 31;
                int cp = e - row * 31;
                uint32_t h, l;
                cvt_split_h(v.x, v.y, h, l);
                uint32_t off = (uint32_t)row * 128 +
                               (((uint32_t)cp * 4) ^ (((uint32_t)row & 7) << 4));
                STS32U(th + off, h);
                STS32U(tl + off, l);
            }
        }

        // ---- consume slab it: ldmatrix + MMA
        const uint32_t th = sb + (it & 1) * 32768, tl = th + 16384;
        float acc[32];
#pragma unroll
        for (int i = 0; i < 32; i++) acc[i] = 0.0f;

#pragma unroll
        for (int ks = 0; ks < 4; ks++) {
            const uint32_t a = lrowoff + (((uint32_t)(ks * 32) + cbase) ^ lswz);
            uint32_t ah0, ah1, ah2, ah3, al0, al1, al2, al3;
            LDMATRIX_X4(ah0, ah1, ah2, ah3, th + a);
            LDMATRIX_X4(al0, al1, al2, al3, tl + a);
#pragma unroll
            for (int nt = 0; nt < 8; nt++) {
                const int bi = ks * 8 + nt;
                mma16816h(acc[nt*4+0], acc[nt*4+1], acc[nt*4+2], acc[nt*4+3],
                          ah0, ah1, ah2, ah3, BH0[bi], BH1[bi]);
                mma16816h(acc[nt*4+0], acc[nt*4+1], acc[nt*4+2], acc[nt*4+3],
                          al0, al1, al2, al3, BH0[bi], BH1[bi]);
            }
        }

        // ---- epilogue: fragments -> swizzled warp tile -> +affine -> STG.128
        {
            const int qhi = q >> 1, qlo = q & 1;
#pragma unroll
            for (int nt = 0; nt < 8; nt++) {
                uint32_t f4a = (uint32_t)((2 * nt + qhi) ^ g);
                uint32_t f4b = (uint32_t)((2 * nt + qhi) ^ (g + 8));
                STS64F(wb + g * 256 + f4a * 16 + qlo * 8,       acc[nt*4+0], acc[nt*4+1]);
                STS64F(wb + (g + 8) * 256 + f4b * 16 + qlo * 8, acc[nt*4+2], acc[nt*4+3]);
            }
        }
        __syncwarp();
        {
            float* obase = out + (cta_row0 + (long long)it * SLAB_ROWS + warp * 16) * 64;
            const float tbase = (float)(tcta + it * SLAB_ROWS + warp * 16);
#pragma unroll
            for (int i = 0; i < 8; i++) {
                int slot = i * 32 + lane;
                int row = slot >> 4;
                int c4 = slot & 15;
                uint32_t f4 = (uint32_t)(c4 ^ row);
                float f0, f1, f2, f3;
                LDS128F(f0, f1, f2, f3, wb + row * 256 + f4 * 16);
                float4 cr = *(const float4*)(scorr + c4 * 4);
                float4 wt = *(const float4*)(scorr + 64 + c4 * 4);
                float tv = tbase + (float)row;
                f0 += cr.x + tv * wt.x;
                f1 += cr.y + tv * wt.y;
                f2 += cr.z + tv * wt.z;
                f3 += cr.w + tv * wt.w;
                *(float4*)(obase + row * 64 + c4 * 4) = make_float4(f0, f1, f2, f3);
            }
        }

        __syncthreads();   // next buffer fully produced; this buffer free
    }
}

// ---------------------------------------------------------------------------
extern "C" void kernel_launch(void* const* d_in, const int* in_sizes, int n_in,
                              void* d_out, int out_size) {
    const float* market = (const float*)d_in[0];
    build_weff<<<1, 256>>>((const float*)d_in[1], (const float*)d_in[2],
                           (const float*)d_in[3], (const float*)d_in[4],
                           (const float*)d_in[5], (const float*)d_in[6]);

    cudaFuncSetAttribute((const void*)encode_kernel,
                         cudaFuncAttributeMaxDynamicSharedMemorySize, SM_TOTAL);
    const int nblocks = (NSYMS * NSTEPS) / (ITERS * SLAB_ROWS);   // 2048
    encode_kernel<<<nblocks, 256, SM_TOTAL>>>(market, (float*)d_out);
}

// round 13
// speedup vs baseline: 1.3202x; 1.3202x over previous
#include <cuda_runtime.h>
#include <cuda_fp16.h>
#include <cstdint>

#define NSYMS  256
#define NSTEPS 8192
#define NCH    62
#define HID    16

// ===========================================================================
// fp16 B fragments for mma.m16n8k16 (market cols only; k=62,63 zeroed):
//   g_Bfrag16[(ks*8+nt)*32 + lane] = { h01, h89 }
// g_Wst[0..63] = W_eff[o][sym], g_Wst[64..127] = W_eff[o][t]  (fp32, exact)
// ===========================================================================
__device__ uint2 g_Bfrag16[4 * 8 * 32];
__device__ float g_Wst[128];

__global__ void build_weff(const float* __restrict__ W1h, const float* __restrict__ M1h,
                           const float* __restrict__ W2h, const float* __restrict__ M2h,
                           const float* __restrict__ W3h, const float* __restrict__ M3h) {
    __shared__ float W1[HID * 64];
    __shared__ float W2[HID * HID];
    __shared__ float W3[64 * HID];
    __shared__ float T2[HID * 64];
    __shared__ float Wt[64 * 64];   // [cin][o]
    const int tid = threadIdx.x;

    for (int i = tid; i < HID * 64; i += 256)
        W1[i] = tanhf(W1h[i]) * (1.0f / (1.0f + expf(-M1h[i])));
    for (int i = tid; i < HID * HID; i += 256)
        W2[i] = tanhf(W2h[i]) * (1.0f / (1.0f + expf(-M2h[i])));
    for (int i = tid; i < 64 * HID; i += 256)
        W3[i] = tanhf(W3h[i]) * (1.0f / (1.0f + expf(-M3h[i])));
    __syncthreads();

    for (int i = tid; i < HID * 64; i += 256) {
        int h = i >> 6, c = i & 63;
        float s = 0.0f;
#pragma unroll
        for (int k = 0; k < HID; k++) s += W2[h * HID + k] * W1[k * 64 + c];
        T2[i] = s;
    }
    __syncthreads();

    for (int i = tid; i < 64 * 64; i += 256) {
        int o = i >> 6, c = i & 63;
        float s = 0.0f;
#pragma unroll
        for (int k = 0; k < HID; k++) s += W3[o * HID + k] * T2[k * 64 + c];
        Wt[c * 64 + o] = s;
    }
    __syncthreads();

    for (int i = tid; i < 1024; i += 256) {
        int lane = i & 31, nt = (i >> 5) & 7, ks = i >> 8;
        int g = lane >> 2, q = lane & 3;
        int n = nt * 8 + g;
        int k0 = ks * 16 + 2 * q;
        float w[4];
#pragma unroll
        for (int j = 0; j < 4; j++) {
            int k = k0 + (j >> 1) * 8 + (j & 1);
            w[j] = (k < 62) ? Wt[(k + 2) * 64 + n] : 0.0f;
        }
        __half2 h01 = __floats2half2_rn(w[0], w[1]);
        __half2 h89 = __floats2half2_rn(w[2], w[3]);
        uint2 u;
        u.x = *reinterpret_cast<uint32_t*>(&h01);
        u.y = *reinterpret_cast<uint32_t*>(&h89);
        g_Bfrag16[i] = u;
    }
    for (int i = tid; i < 128; i += 256)
        g_Wst[i] = Wt[i];
}

// ===========================================================================
// PTX helpers
// ===========================================================================
__device__ __forceinline__ void mma16816h(float& d0, float& d1, float& d2, float& d3,
                                          uint32_t a0, uint32_t a1, uint32_t a2, uint32_t a3,
                                          uint32_t b0, uint32_t b1) {
    asm volatile("mma.sync.aligned.m16n8k16.row.col.f32.f16.f16.f32 "
                 "{%0,%1,%2,%3}, {%4,%5,%6,%7}, {%8,%9}, {%0,%1,%2,%3};"
                 : "+f"(d0), "+f"(d1), "+f"(d2), "+f"(d3)
                 : "r"(a0), "r"(a1), "r"(a2), "r"(a3), "r"(b0), "r"(b1));
}
__device__ __forceinline__ void cvt_split_h(float x, float y, uint32_t& h, uint32_t& l) {
    __half2 h2 = __floats2half2_rn(x, y);
    float2 hf = __half22float2(h2);
    __half2 l2 = __floats2half2_rn(x - hf.x, y - hf.y);
    h = *reinterpret_cast<uint32_t*>(&h2);
    l = *reinterpret_cast<uint32_t*>(&l2);
}
__device__ __forceinline__ uint32_t smem_u32(const void* p) {
    uint32_t a;
    asm("{ .reg .u64 t; cvta.to.shared.u64 t, %1; cvt.u32.u64 %0, t; }" : "=r"(a) : "l"(p));
    return a;
}
__device__ __forceinline__ void mbar_init(uint32_t mbar, uint32_t cnt) {
    asm volatile("mbarrier.init.shared.b64 [%0], %1;" :: "r"(mbar), "r"(cnt) : "memory");
}
__device__ __forceinline__ void mbar_expect_tx(uint32_t mbar, uint32_t bytes) {
    asm volatile("mbarrier.arrive.expect_tx.shared.b64 _, [%0], %1;" :: "r"(mbar), "r"(bytes) : "memory");
}
__device__ __forceinline__ void mbar_wait(uint32_t mbar, uint32_t parity) {
    asm volatile("{\n\t.reg .pred P1;\n\tWL_%=:\n\t"
                 "mbarrier.try_wait.parity.acquire.cta.shared::cta.b64 P1, [%0], %1, 0x989680;\n\t"
                 "@P1 bra.uni WD_%=;\n\tbra.uni WL_%=;\n\tWD_%=:\n\t}"
                 :: "r"(mbar), "r"(parity) : "memory");
}
__device__ __forceinline__ void bulk_g2s(uint32_t dst, const void* src, uint32_t bytes, uint32_t mbar) {
    asm volatile("cp.async.bulk.shared::cta.global.mbarrier::complete_tx::bytes [%0], [%1], %2, [%3];"
                 :: "r"(dst), "l"(src), "r"(bytes), "r"(mbar) : "memory");
}
#define FENCE_ASYNC() asm volatile("fence.proxy.async.shared::cta;" ::: "memory")
#define LDS64F(f0, f1, a) \
    asm volatile("ld.shared.v2.f32 {%0, %1}, [%2];" : "=f"(f0), "=f"(f1) : "r"(a))
#define STS64F(a, f0, f1) \
    asm volatile("st.shared.v2.f32 [%0], {%1, %2};" :: "r"(a), "f"(f0), "f"(f1) : "memory")
#define LDS128F(f0, f1, f2, f3, a) \
    asm volatile("ld.shared.v4.f32 {%0, %1, %2, %3}, [%4];" : "=f"(f0), "=f"(f1), "=f"(f2), "=f"(f3) : "r"(a))

// ===========================================================================
// Main kernel: bulk-copy double-buffered staging + fp16 2-term MMA.
//   CTA: 256 thr = 8 warps; warp = 16 rows x ALL 64 outs (A gathered once).
//   ITERS=8 slabs x 128 rows = 1024 rows/CTA; grid 2048.
//   LDS.64 gather from 248B-stride staged rows: bank = 30g + 2q mod 32,
//   all 32 lanes distinct -> conflict-free.
// ===========================================================================
#define ITERS      8
#define SLAB_ROWS  128
#define ROW_BYTES  248
#define SLAB_BYTES (SLAB_ROWS * ROW_BYTES)    // 31744 (16B multiple)
#define SM_EPI     (2 * SLAB_BYTES)           // 63488: 8 x 4KB warp tiles
#define SM_SCORR   (SM_EPI + 32768)           // 96256
#define SM_MBAR    (SM_SCORR + 512)           // 96768
#define SM_TOTAL   (SM_MBAR + 64)

__global__ void __launch_bounds__(256, 1)
encode_kernel(const float* __restrict__ market, float* __restrict__ out) {
    extern __shared__ char smem[];
    const uint32_t sb = smem_u32(smem);
    const int tid  = threadIdx.x;
    const int warp = tid >> 5;     // row group: 16 rows of each slab
    const int lane = tid & 31;
    const int g = lane >> 2;       // 0..7
    const int q = lane & 3;        // 0..3

    // ---- B fragments: 64 regs (full N)
    uint32_t BH0[32], BH1[32];
#pragma unroll
    for (int i = 0; i < 32; i++) {
        uint2 u = g_Bfrag16[i * 32 + lane];
        BH0[i] = u.x; BH1[i] = u.y;
    }

    const long long cta_row0 = (long long)blockIdx.x * (ITERS * SLAB_ROWS);  // 1024-aligned
    const float sval = (float)(cta_row0 >> 13);
    const int   tcta = (int)(cta_row0 & (NSTEPS - 1));
    const char* srcbase = (const char*)market + cta_row0 * ROW_BYTES;

    if (tid < 64) {
        ((float*)(smem + SM_SCORR))[tid]      = sval * g_Wst[tid];
        ((float*)(smem + SM_SCORR))[64 + tid] = g_Wst[64 + tid];
    }
    if (tid == 0) {
        mbar_init(sb + SM_MBAR, 1);
        mbar_init(sb + SM_MBAR + 8, 1);
        FENCE_ASYNC();
    }
    __syncthreads();

    // ---- issue slabs 0,1
    if (tid == 0) {
#pragma unroll
        for (int s = 0; s < 2; s++) {
            uint32_t mb = sb + SM_MBAR + s * 8;
            mbar_expect_tx(mb, SLAB_BYTES);
            bulk_g2s(sb + s * SLAB_BYTES, srcbase + (size_t)s * SLAB_BYTES, SLAB_BYTES, mb);
        }
    }

    const uint32_t wb = sb + SM_EPI + warp * 4096;   // per-warp 16x64 fp32 epi tile
    const float* scorr = (const float*)(smem + SM_SCORR);

#pragma unroll 1
    for (int it = 0; it < ITERS; it++) {
        mbar_wait(sb + SM_MBAR + (it & 1) * 8, (it >> 1) & 1);

        // ---- gather fragments from staged slab (conflict-free LDS.64)
        const uint32_t ab = sb + (it & 1) * SLAB_BYTES + (warp * 16 + g) * ROW_BYTES;
        float2 vc[16];   // [ks*4 + {p0 pair0, p0 pair1, p1 pair0, p1 pair1}]
#pragma unroll
        for (int ks = 0; ks < 4; ks++) {
            const uint32_t c0b = (uint32_t)(ks * 16 + 2 * q) * 4;
            LDS64F(vc[ks*4+0].x, vc[ks*4+0].y, ab + c0b);
            LDS64F(vc[ks*4+2].x, vc[ks*4+2].y, ab + 8 * ROW_BYTES + c0b);
            if (ks == 3 && q == 3) {
                vc[13] = make_float2(0.0f, 0.0f);    // cols 62,63: exact affine
                vc[15] = make_float2(0.0f, 0.0f);
            } else {
                LDS64F(vc[ks*4+1].x, vc[ks*4+1].y, ab + c0b + 32);
                LDS64F(vc[ks*4+3].x, vc[ks*4+3].y, ab + 8 * ROW_BYTES + c0b + 32);
            }
        }
        __syncthreads();   // whole CTA done reading this stage buffer

        // ---- refill this buffer with slab it+2 (overlaps MMA + epilogue)
        if (it + 2 < ITERS && tid == 0) {
            uint32_t mb = sb + SM_MBAR + (it & 1) * 8;
            mbar_expect_tx(mb, SLAB_BYTES);
            bulk_g2s(sb + (it & 1) * SLAB_BYTES,
                     srcbase + (size_t)(it + 2) * SLAB_BYTES, SLAB_BYTES, mb);
        }

        // ---- convert + MMA: D = (Ah + Al) * Bh, fp32 accum
        float acc[32];
#pragma unroll
        for (int i = 0; i < 32; i++) acc[i] = 0.0f;

#pragma unroll
        for (int ks = 0; ks < 4; ks++) {
            uint32_t ah0, ah1, ah2, ah3, al0, al1, al2, al3;
            cvt_split_h(vc[ks*4+0].x, vc[ks*4+0].y, ah0, al0);   // row g,   pair0
            cvt_split_h(vc[ks*4+2].x, vc[ks*4+2].y, ah1, al1);   // row g+8, pair0
            cvt_split_h(vc[ks*4+1].x, vc[ks*4+1].y, ah2, al2);   // row g,   pair1
            cvt_split_h(vc[ks*4+3].x, vc[ks*4+3].y, ah3, al3);   // row g+8, pair1
#pragma unroll
            for (int nt = 0; nt < 8; nt++) {
                const int bi = ks * 8 + nt;
                mma16816h(acc[nt*4+0], acc[nt*4+1], acc[nt*4+2], acc[nt*4+3],
                          ah0, ah1, ah2, ah3, BH0[bi], BH1[bi]);
                mma16816h(acc[nt*4+0], acc[nt*4+1], acc[nt*4+2], acc[nt*4+3],
                          al0, al1, al2, al3, BH0[bi], BH1[bi]);
            }
        }

        // ---- epilogue: fragments -> swizzled warp tile -> +affine -> STG.128
        {
            const int qhi = q >> 1, qlo = q & 1;
#pragma unroll
            for (int nt = 0; nt < 8; nt++) {
                uint32_t f4a = (uint32_t)((2 * nt + qhi) ^ g);
                uint32_t f4b = (uint32_t)((2 * nt + qhi) ^ (g + 8));
                STS64F(wb + g * 256 + f4a * 16 + qlo * 8,       acc[nt*4+0], acc[nt*4+1]);
                STS64F(wb + (g + 8) * 256 + f4b * 16 + qlo * 8, acc[nt*4+2], acc[nt*4+3]);
            }
        }
        __syncwarp();
        {
            float* obase = out + (cta_row0 + (long long)it * SLAB_ROWS + warp * 16) * 64;
            const float tbase = (float)(tcta + it * SLAB_ROWS + warp * 16);
#pragma unroll
            for (int i = 0; i < 8; i++) {
                int slot = i * 32 + lane;
                int row = slot >> 4;
                int c4 = slot & 15;
                uint32_t f4 = (uint32_t)(c4 ^ row);
                float f0, f1, f2, f3;
                LDS128F(f0, f1, f2, f3, wb + row * 256 + f4 * 16);
                float4 cr = *(const float4*)(scorr + c4 * 4);
                float4 wt = *(const float4*)(scorr + 64 + c4 * 4);
                float tv = tbase + (float)row;
                f0 += cr.x + tv * wt.x;
                f1 += cr.y + tv * wt.y;
                f2 += cr.z + tv * wt.z;
                f3 += cr.w + tv * wt.w;
                *(float4*)(obase + row * 64 + c4 * 4) = make_float4(f0, f1, f2, f3);
            }
        }
        __syncwarp();
    }
}

// ---------------------------------------------------------------------------
extern "C" void kernel_launch(void* const* d_in, const int* in_sizes, int n_in,
                              void* d_out, int out_size) {
    const float* market = (const float*)d_in[0];
    build_weff<<<1, 256>>>((const float*)d_in[1], (const float*)d_in[2],
                           (const float*)d_in[3], (const float*)d_in[4],
                           (const float*)d_in[5], (const float*)d_in[6]);

    cudaFuncSetAttribute((const void*)encode_kernel,
                         cudaFuncAttributeMaxDynamicSharedMemorySize, SM_TOTAL);
    const int nblocks = (NSYMS * NSTEPS) / (ITERS * SLAB_ROWS);   // 2048
    encode_kernel<<<nblocks, 256, SM_TOTAL>>>(market, (float*)d_out);
}